// round 5
// baseline (speedup 1.0000x reference)
#include <cuda_runtime.h>
#include <cuda_bf16.h>
#include <cstdint>

// CrossInferenceBlock, bf16x3 split-precision via mma.sync (HMMA), reassociated:
//  tp    = batch @ [a_w|b_w] + [a_b|b_b]   (65536 x 512)   theta|phi, bf16 hi/lo
//  attn[t] = theta[t] @ phi[t]^T           (256 x 256)     bf16 hi/lo
//  rowsum[m] = sum_r attn[m][r]
//  tmp[t]  = attn[t] @ batch[t]            (256 x 1024)    bf16 hi/lo  (NN, ldsm.trans)
//  out     = (tmp @ g_w + rowsum*g_b^T)/512                fp32        (NN, ldsm.trans)

#define TT 256
#define SS 256
#define FF 1024
#define AA 256

typedef __nv_bfloat16 bf16;

// ------------------------------- static scratch
__device__ __align__(16) bf16 g_batchH[67108864];
__device__ __align__(16) bf16 g_batchL[67108864];
__device__ __align__(16) bf16 g_wTH[524288];       // [512][1024] = aT|bT
__device__ __align__(16) bf16 g_wTL[524288];
__device__ __align__(16) bf16 g_gwH[1048576];      // g_w split, not transposed
__device__ __align__(16) bf16 g_gwL[1048576];
__device__ __align__(16) bf16 g_tpH[33554432];     // [65536][512]
__device__ __align__(16) bf16 g_tpL[33554432];
__device__ __align__(16) bf16 g_attnH[16777216];   // [65536][256]
__device__ __align__(16) bf16 g_attnL[16777216];
__device__ __align__(16) bf16 g_tmpH[67108864];    // [65536][1024]
__device__ __align__(16) bf16 g_tmpL[67108864];
__device__ __align__(16) float g_rowsum[65536];

// ------------------------------- helpers
__device__ __forceinline__ uint32_t smem_u32(const void* p) {
    uint32_t a;
    asm("{ .reg .u64 t; cvta.to.shared.u64 t, %1; cvt.u32.u64 %0, t; }"
        : "=r"(a) : "l"(p));
    return a;
}
__device__ __forceinline__ void cpasync16(uint32_t s, const void* g) {
    asm volatile("cp.async.cg.shared.global [%0], [%1], 16;" :: "r"(s), "l"(g));
}
__device__ __forceinline__ void cp_commit() { asm volatile("cp.async.commit_group;"); }
template <int N>
__device__ __forceinline__ void cp_wait() {
    asm volatile("cp.async.wait_group %0;" :: "n"(N));
}
__device__ __forceinline__ uint4 ldsm4(uint32_t a) {
    uint4 r;
    asm volatile("ldmatrix.sync.aligned.m8n8.x4.shared.b16 {%0,%1,%2,%3}, [%4];"
                 : "=r"(r.x), "=r"(r.y), "=r"(r.z), "=r"(r.w) : "r"(a));
    return r;
}
__device__ __forceinline__ uint4 ldsm4t(uint32_t a) {
    uint4 r;
    asm volatile("ldmatrix.sync.aligned.m8n8.x4.trans.shared.b16 {%0,%1,%2,%3}, [%4];"
                 : "=r"(r.x), "=r"(r.y), "=r"(r.z), "=r"(r.w) : "r"(a));
    return r;
}
__device__ __forceinline__ void mma_bf16(float* c, const uint4& a,
                                         uint32_t b0, uint32_t b1) {
    asm volatile(
        "mma.sync.aligned.m16n8k16.row.col.f32.bf16.bf16.f32 "
        "{%0,%1,%2,%3},{%4,%5,%6,%7},{%8,%9},{%0,%1,%2,%3};"
        : "+f"(c[0]), "+f"(c[1]), "+f"(c[2]), "+f"(c[3])
        : "r"(a.x), "r"(a.y), "r"(a.z), "r"(a.w), "r"(b0), "r"(b1));
}
__device__ __forceinline__ void split2(float v0, float v1, uint32_t& h, uint32_t& l) {
    asm("cvt.rn.bf16x2.f32 %0, %1, %2;" : "=r"(h) : "f"(v1), "f"(v0));
    float h0 = __uint_as_float(h << 16);
    float h1 = __uint_as_float(h & 0xFFFF0000u);
    asm("cvt.rn.bf16x2.f32 %0, %1, %2;" : "=r"(l) : "f"(v1 - h1), "f"(v0 - h0));
}

// ------------------------------- converters
__global__ void split_kernel(const float* __restrict__ in,
                             bf16* __restrict__ oh, bf16* __restrict__ ol, long n) {
    long i = ((long)blockIdx.x * blockDim.x + threadIdx.x) * 4;
    if (i >= n) return;
    float4 v = *(const float4*)(in + i);
    uint32_t h0, l0, h1, l1;
    split2(v.x, v.y, h0, l0);
    split2(v.z, v.w, h1, l1);
    *(uint2*)(oh + i) = make_uint2(h0, h1);
    *(uint2*)(ol + i) = make_uint2(l0, l1);
}

__global__ void transpose_split_kernel(const float* __restrict__ in,
                                       bf16* __restrict__ oh, bf16* __restrict__ ol,
                                       int R, int C) {
    __shared__ float t[32][33];
    int c0 = blockIdx.x * 32, r0 = blockIdx.y * 32;
    int x = threadIdx.x, y = threadIdx.y;  // 32 x 8
#pragma unroll
    for (int i = 0; i < 32; i += 8)
        t[y + i][x] = in[(long)(r0 + y + i) * C + c0 + x];
    __syncthreads();
#pragma unroll
    for (int i = 0; i < 32; i += 8) {
        float v = t[x][y + i];
        bf16 hb = __float2bfloat16(v);
        float lo = v - __bfloat162float(hb);
        long o = (long)(c0 + y + i) * R + r0 + x;
        oh[o] = hb;
        ol[o] = __float2bfloat16(lo);
    }
}

__global__ void rowsum_kernel(const bf16* __restrict__ H, const bf16* __restrict__ L,
                              float* __restrict__ out) {
    int m = blockIdx.x * 4 + (threadIdx.x >> 5);
    int lane = threadIdx.x & 31;
    const uint4 h4 = *(const uint4*)(H + (long)m * 256 + lane * 8);
    const uint4 l4 = *(const uint4*)(L + (long)m * 256 + lane * 8);
    float s = 0.0f;
    const uint32_t w[8] = {h4.x, h4.y, h4.z, h4.w, l4.x, l4.y, l4.z, l4.w};
#pragma unroll
    for (int i = 0; i < 8; i++) {
        s += __uint_as_float(w[i] << 16);
        s += __uint_as_float(w[i] & 0xFFFF0000u);
    }
#pragma unroll
    for (int o = 16; o > 0; o >>= 1)
        s += __shfl_xor_sync(0xFFFFFFFF, s, o);
    if (lane == 0) out[m] = s;
}

// ------------------------------- GEMM: BM=128 BN=128 BK=64, 3-stage cp.async
static constexpr int STAGE  = 65536;
static constexpr int OFF_AH = 0;
static constexpr int OFF_AL = 16384;
static constexpr int OFF_BH = 32768;
static constexpr int OFF_BL = 49152;
static constexpr int SMEMB  = 3 * STAGE;   // 192 KB

// TRANSB: B stored [K][N] row-major (NN GEMM, ldsm.trans); else B [N][K] (NT).
// BMODE: 0 none, 1 col-bias (bias for n<256, bias2 for n>=256), 3 rank-1 (bias[m]*bias2[n])
template <bool TRANSB, int BMODE, bool SPLIT>
__global__ void __launch_bounds__(256) gemm_hmma(
    const bf16* __restrict__ Ah, const bf16* __restrict__ Al,
    const bf16* __restrict__ Bh, const bf16* __restrict__ Bl,
    const float* __restrict__ bias, const float* __restrict__ bias2,
    bf16* __restrict__ Ch, bf16* __restrict__ Cl, float* __restrict__ Cf,
    int N, int K, int lda, int ldb, int ldc, float scale,
    long sA, long sB, long sC)
{
    extern __shared__ __align__(1024) char smem[];
    const uint32_t sbase = smem_u32(smem);
    const int tid = threadIdx.x;
    const int wid = tid >> 5, lane = tid & 31;
    const long z = blockIdx.z;
    const int block_row = blockIdx.y * 128;
    const int block_col = blockIdx.x * 128;

    const bf16* Az_h = Ah + z * sA + (long)block_row * lda;
    const bf16* Az_l = Al + z * sA + (long)block_row * lda;
    const bf16* Bz_h;
    const bf16* Bz_l;
    if (TRANSB) { Bz_h = Bh + z * sB + block_col;            Bz_l = Bl + z * sB + block_col; }
    else        { Bz_h = Bh + z * sB + (long)block_col * ldb; Bz_l = Bl + z * sB + (long)block_col * ldb; }

    // per-thread cp.async chunk mappings (4 chunks per 16KB tile)
    int a_row[4]; uint32_t a_so[4]; int a_co[4];
    int b_row[4]; uint32_t b_so[4]; int b_co[4];
#pragma unroll
    for (int i = 0; i < 4; i++) {
        int q = tid + i * 256;
        {   // A tile: 128 rows x 8 units (128B rows)
            int r = q >> 3, u = q & 7;
            a_row[i] = r; a_co[i] = u * 8;
            a_so[i] = (uint32_t)(r * 128 + ((u ^ (r & 7)) << 4));
        }
        if (TRANSB) {  // B tile: 64 k-rows x 16 units (256B rows)
            int r = q >> 4, u = q & 15;
            b_row[i] = r; b_co[i] = u * 8;
            b_so[i] = (uint32_t)(r * 256 + ((u ^ (r & 7)) << 4));
        } else {       // B tile: 128 n-rows x 8 units
            int r = q >> 3, u = q & 7;
            b_row[i] = r; b_co[i] = u * 8;
            b_so[i] = (uint32_t)(r * 128 + ((u ^ (r & 7)) << 4));
        }
    }

    auto load_stage = [&](int buf, int k0) {
        uint32_t sb = sbase + buf * STAGE;
#pragma unroll
        for (int i = 0; i < 4; i++) {
            long ga = (long)a_row[i] * lda + k0 + a_co[i];
            cpasync16(sb + OFF_AH + a_so[i], Az_h + ga);
            cpasync16(sb + OFF_AL + a_so[i], Az_l + ga);
            long gb;
            if (TRANSB) gb = (long)(k0 + b_row[i]) * ldb + b_co[i];
            else        gb = (long)b_row[i] * ldb + k0 + b_co[i];
            cpasync16(sb + OFF_BH + b_so[i], Bz_h + gb);
            cpasync16(sb + OFF_BL + b_so[i], Bz_l + gb);
        }
    };

    // warp tiling: 2(m) x 4(n), 64x32 per warp
    const int wm = wid & 1, wn = wid >> 1;
    const int arow = wm * 64 + (lane & 15);
    const uint32_t asel = ((lane >> 4) & 1) * 16;
    const uint32_t axr = (uint32_t)((arow & 7) << 4);
    // NT-path B ldsm addressing
    const int brow = wn * 32 + (lane & 7) + ((lane & 16) ? 8 : 0);
    const uint32_t bsel = (lane & 8) ? 16u : 0u;
    const uint32_t bxr = (uint32_t)((brow & 7) << 4);
    // NN-path (trans) B ldsm addressing
    const int tkrow = (lane & 7) + ((lane & 8) ? 8 : 0);
    const int tnsel = (lane & 16) ? 8 : 0;

    float acc[4][4][4];
#pragma unroll
    for (int a = 0; a < 4; a++)
#pragma unroll
        for (int b = 0; b < 4; b++)
#pragma unroll
            for (int c = 0; c < 4; c++) acc[a][b][c] = 0.0f;

    const int NT = K >> 6;
    load_stage(0, 0);
    cp_commit();
    if (NT > 1) load_stage(1, 64);
    cp_commit();

    int buf = 0;
    for (int it = 0; it < NT; it++) {
        cp_wait<1>();
        __syncthreads();
        if (it + 2 < NT) load_stage((it + 2) % 3, (it + 2) << 6);
        cp_commit();

        const uint32_t sb = sbase + buf * STAGE;
#pragma unroll
        for (int kk = 0; kk < 4; kk++) {
            uint4 ah[4], al4[4], bhf[2], blf[2];
#pragma unroll
            for (int mi = 0; mi < 4; mi++) {
                uint32_t ro = (uint32_t)((arow + mi * 16) * 128) +
                              (((uint32_t)(kk * 32) + asel) ^ axr);
                ah[mi] = ldsm4(sb + OFF_AH + ro);
                al4[mi] = ldsm4(sb + OFF_AL + ro);
            }
            if (TRANSB) {
#pragma unroll
                for (int pi = 0; pi < 2; pi++) {
                    int krow = kk * 16 + tkrow;
                    int ncol = wn * 32 + pi * 16 + tnsel;
                    uint32_t ro = (uint32_t)(krow * 256 +
                                   (((ncol >> 3) ^ (krow & 7)) << 4));
                    bhf[pi] = ldsm4t(sb + OFF_BH + ro);
                    blf[pi] = ldsm4t(sb + OFF_BL + ro);
                }
            } else {
#pragma unroll
                for (int pi = 0; pi < 2; pi++) {
                    uint32_t ro = (uint32_t)((brow + pi * 16) * 128) +
                                  (((uint32_t)(kk * 32) + bsel) ^ bxr);
                    bhf[pi] = ldsm4(sb + OFF_BH + ro);
                    blf[pi] = ldsm4(sb + OFF_BL + ro);
                }
            }
#pragma unroll
            for (int mi = 0; mi < 4; mi++) {
#pragma unroll
                for (int ni = 0; ni < 4; ni++) {
                    const int pi = ni >> 1;
                    const bool up = ni & 1;
                    uint32_t bh0 = up ? bhf[pi].z : bhf[pi].x;
                    uint32_t bh1 = up ? bhf[pi].w : bhf[pi].y;
                    uint32_t bl0 = up ? blf[pi].z : blf[pi].x;
                    uint32_t bl1 = up ? blf[pi].w : blf[pi].y;
                    mma_bf16(acc[mi][ni], ah[mi], bh0, bh1);
                    mma_bf16(acc[mi][ni], ah[mi], bl0, bl1);
                    mma_bf16(acc[mi][ni], al4[mi], bh0, bh1);
                }
            }
        }
        buf = (buf + 1) % 3;
    }

    // ------------------ epilogue
    const int grow0 = block_row + wm * 64 + (lane >> 2);
    const int gcol0 = block_col + wn * 32 + (lane & 3) * 2;
#pragma unroll
    for (int mi = 0; mi < 4; mi++) {
#pragma unroll
        for (int ni = 0; ni < 4; ni++) {
            float v0 = acc[mi][ni][0], v1 = acc[mi][ni][1];
            float v2 = acc[mi][ni][2], v3 = acc[mi][ni][3];
            const int r0 = grow0 + mi * 16, r1 = r0 + 8;
            const int cc = gcol0 + ni * 8;
            if (BMODE == 1) {
                float b0 = (cc < 256) ? bias[cc] : bias2[cc - 256];
                float b1 = (cc + 1 < 256) ? bias[cc + 1] : bias2[cc + 1 - 256];
                v0 += b0; v1 += b1; v2 += b0; v3 += b1;
            }
            if (BMODE == 3) {
                float gb0 = bias2[cc], gb1 = bias2[cc + 1];
                float ra = bias[r0], rb = bias[r1];
                v0 += ra * gb0; v1 += ra * gb1; v2 += rb * gb0; v3 += rb * gb1;
            }
            v0 *= scale; v1 *= scale; v2 *= scale; v3 *= scale;
            const long o0 = z * sC + (long)r0 * ldc + cc;
            const long o1 = z * sC + (long)r1 * ldc + cc;
            if (SPLIT) {
                uint32_t h, l;
                split2(v0, v1, h, l);
                *(uint32_t*)(Ch + o0) = h;
                *(uint32_t*)(Cl + o0) = l;
                split2(v2, v3, h, l);
                *(uint32_t*)(Ch + o1) = h;
                *(uint32_t*)(Cl + o1) = l;
            } else {
                *(float2*)(Cf + o0) = make_float2(v0, v1);
                *(float2*)(Cf + o1) = make_float2(v2, v3);
            }
        }
    }
}

// ------------------------------- launcher
extern "C" void kernel_launch(void* const* d_in, const int* in_sizes, int n_in,
                              void* d_out, int out_size)
{
    const float* batch = (const float*)d_in[0];
    const float* a_w   = (const float*)d_in[1];
    const float* a_b   = (const float*)d_in[2];
    const float* b_w   = (const float*)d_in[3];
    const float* b_b   = (const float*)d_in[4];
    const float* g_w   = (const float*)d_in[5];
    const float* g_b   = (const float*)d_in[6];
    float* out = (float*)d_out;

    void* p;
#define SYMB(v, s) cudaGetSymbolAddress(&p, s); bf16* v = (bf16*)p
    SYMB(batchH, g_batchH);  SYMB(batchL, g_batchL);
    SYMB(wTH, g_wTH);        SYMB(wTL, g_wTL);
    SYMB(gwH, g_gwH);        SYMB(gwL, g_gwL);
    SYMB(tpH, g_tpH);        SYMB(tpL, g_tpL);
    SYMB(attnH, g_attnH);    SYMB(attnL, g_attnL);
    SYMB(tmpH, g_tmpH);      SYMB(tmpL, g_tmpL);
#undef SYMB
    cudaGetSymbolAddress(&p, g_rowsum); float* rowsum = (float*)p;

    static bool attr_done = false;
    if (!attr_done) {
        cudaFuncSetAttribute(gemm_hmma<false, 1, true>,
                             cudaFuncAttributeMaxDynamicSharedMemorySize, SMEMB);
        cudaFuncSetAttribute(gemm_hmma<false, 0, true>,
                             cudaFuncAttributeMaxDynamicSharedMemorySize, SMEMB);
        cudaFuncSetAttribute(gemm_hmma<true, 0, true>,
                             cudaFuncAttributeMaxDynamicSharedMemorySize, SMEMB);
        cudaFuncSetAttribute(gemm_hmma<true, 3, false>,
                             cudaFuncAttributeMaxDynamicSharedMemorySize, SMEMB);
        attr_done = true;
    }

    // converts
    split_kernel<<<65536, 256>>>(batch, batchH, batchL, (long)67108864);
    const dim3 tb(32, 8);
    transpose_split_kernel<<<dim3(AA / 32, FF / 32), tb>>>(a_w, wTH, wTL, FF, AA);
    transpose_split_kernel<<<dim3(AA / 32, FF / 32), tb>>>(
        b_w, wTH + 256 * 1024, wTL + 256 * 1024, FF, AA);
    split_kernel<<<1024, 256>>>(g_w, gwH, gwL, (long)1048576);

    // tp = batch @ [a_w|b_w] + bias : M=65536, N=512, K=1024 (NT)
    gemm_hmma<false, 1, true><<<dim3(4, 512, 1), 256, SMEMB>>>(
        batchH, batchL, wTH, wTL, a_b, b_b, tpH, tpL, nullptr,
        512, 1024, 1024, 1024, 512, 1.0f, 0, 0, 0);

    // attn[t] = theta[t] @ phi[t]^T : per t M=N=256, K=256 (NT)
    gemm_hmma<false, 0, true><<<dim3(2, 2, 256), 256, SMEMB>>>(
        tpH, tpL, tpH + 256, tpL + 256, nullptr, nullptr, attnH, attnL, nullptr,
        256, 256, 512, 512, 256, 1.0f, 131072, 131072, 65536);

    rowsum_kernel<<<16384, 128>>>(attnH, attnL, rowsum);

    // tmp[t] = attn[t] @ batch[t] : per t M=256, N=1024, K=256 (NN, trans-B)
    gemm_hmma<true, 0, true><<<dim3(8, 2, 256), 256, SMEMB>>>(
        attnH, attnL, batchH, batchL, nullptr, nullptr, tmpH, tmpL, nullptr,
        1024, 256, 256, 1024, 1024, 1.0f, 65536, 262144, 262144);

    // out = (tmp @ g_w + rowsum*g_b^T)/512 : M=65536, N=1024, K=1024 (NN)
    gemm_hmma<true, 3, false><<<dim3(8, 512, 1), 256, SMEMB>>>(
        tmpH, tmpL, gwH, gwL, rowsum, g_b, nullptr, nullptr, out,
        1024, 1024, 1024, 1024, 1024, 1.0f / (float)(SS + TT), 0, 0, 0);
}

// round 6
// speedup vs baseline: 1.2805x; 1.2805x over previous
#include <cuda_runtime.h>
#include <cuda_fp16.h>
#include <cstdint>

// CrossInferenceBlock via fp16 split-precision mma.sync (HMMA), round-3 dataflow:
//  tp    = batch @ [a_w|b_w] + [a_b|b_b]   (65536 x 512)  2-pass, out hi/lo
//  featsT[t][f][s] = (batch @ g_w + g_b)^T per t          2-pass, out hi/lo
//  attn[t] = theta[t] @ phi[t]^T           (256 x 256)    3-pass, out hi/lo
//  out[t]  = (attn[t] @ feats[t]) / 512                   3-pass, fp32 out
// Every GEMM: C[m][n] = sum_k A[m,k]*B[n,k], K-major fp16 (hi, +lo for B; +Alo in 3-pass).
// 2-pass drops Alo*B (~2e-4 rel); 3-pass drops only Alo*Blo (~2^-22).

#define TT 256
#define SS 256
#define FF 1024
#define AA 256

// ------------------------------- static scratch (fp16 splits)
__device__ __align__(16) __half g_batchH[67108864];
__device__ __align__(16) __half g_batchL[67108864];
__device__ __align__(16) __half g_wTH[524288];       // [512][1024] = aT|bT
__device__ __align__(16) __half g_wTL[524288];
__device__ __align__(16) __half g_gTH[1048576];      // g_w^T  (hi only used)
__device__ __align__(16) __half g_gTL[1048576];
__device__ __align__(16) __half g_tpH[33554432];     // [65536][512] theta|phi
__device__ __align__(16) __half g_tpL[33554432];
__device__ __align__(16) __half g_attnH[16777216];   // [65536][256]
__device__ __align__(16) __half g_attnL[16777216];
__device__ __align__(16) __half g_featsTH[67108864]; // [256][1024][256]
__device__ __align__(16) __half g_featsTL[67108864];

// ------------------------------- helpers
__device__ __forceinline__ uint32_t smem_u32(const void* p) {
    uint32_t a;
    asm("{ .reg .u64 t; cvta.to.shared.u64 t, %1; cvt.u32.u64 %0, t; }"
        : "=r"(a) : "l"(p));
    return a;
}
__device__ __forceinline__ void cpasync16(uint32_t s, const void* g) {
    asm volatile("cp.async.cg.shared.global [%0], [%1], 16;" :: "r"(s), "l"(g));
}
__device__ __forceinline__ void cp_commit() { asm volatile("cp.async.commit_group;"); }
template <int N>
__device__ __forceinline__ void cp_wait() {
    asm volatile("cp.async.wait_group %0;" :: "n"(N));
}
__device__ __forceinline__ uint4 ldsm4(uint32_t a) {
    uint4 r;
    asm volatile("ldmatrix.sync.aligned.m8n8.x4.shared.b16 {%0,%1,%2,%3}, [%4];"
                 : "=r"(r.x), "=r"(r.y), "=r"(r.z), "=r"(r.w) : "r"(a));
    return r;
}
__device__ __forceinline__ void mma_f16(float* c, const uint4& a,
                                        uint32_t b0, uint32_t b1) {
    asm volatile(
        "mma.sync.aligned.m16n8k16.row.col.f32.f16.f16.f32 "
        "{%0,%1,%2,%3},{%4,%5,%6,%7},{%8,%9},{%0,%1,%2,%3};"
        : "+f"(c[0]), "+f"(c[1]), "+f"(c[2]), "+f"(c[3])
        : "r"(a.x), "r"(a.y), "r"(a.z), "r"(a.w), "r"(b0), "r"(b1));
}
// (v0,v1) -> packed fp16x2 hi + fp16x2 lo (lo = residual)
__device__ __forceinline__ void split2h(float v0, float v1, uint32_t& h, uint32_t& l) {
    __half2 hh = __floats2half2_rn(v0, v1);
    float r0 = v0 - __low2float(hh);
    float r1 = v1 - __high2float(hh);
    __half2 ll = __floats2half2_rn(r0, r1);
    h = *(uint32_t*)&hh;
    l = *(uint32_t*)&ll;
}

// ------------------------------- converters
__global__ void split_kernel(const float* __restrict__ in,
                             __half* __restrict__ oh, __half* __restrict__ ol,
                             long n) {
    long i = ((long)blockIdx.x * blockDim.x + threadIdx.x) * 4;
    if (i >= n) return;
    float4 v = *(const float4*)(in + i);
    uint32_t h0, l0, h1, l1;
    split2h(v.x, v.y, h0, l0);
    split2h(v.z, v.w, h1, l1);
    *(uint2*)(oh + i) = make_uint2(h0, h1);
    *(uint2*)(ol + i) = make_uint2(l0, l1);
}

__global__ void transpose_split_kernel(const float* __restrict__ in,
                                       __half* __restrict__ oh,
                                       __half* __restrict__ ol, int R, int C) {
    __shared__ float t[32][33];
    int c0 = blockIdx.x * 32, r0 = blockIdx.y * 32;
    int x = threadIdx.x, y = threadIdx.y;  // 32 x 8
#pragma unroll
    for (int i = 0; i < 32; i += 8)
        t[y + i][x] = in[(long)(r0 + y + i) * C + c0 + x];
    __syncthreads();
#pragma unroll
    for (int i = 0; i < 32; i += 8) {
        float v = t[x][y + i];
        __half hb = __float2half_rn(v);
        float lo = v - __half2float(hb);
        long o = (long)(c0 + y + i) * R + r0 + x;
        oh[o] = hb;
        ol[o] = __float2half_rn(lo);
    }
}

// ------------------------------- GEMM: BM=128 BN=128 BK=64, 3-stage cp.async
static constexpr int TILE = 16384;  // 128 x 64 fp16
static constexpr int OFF_AH = 0;
static constexpr int OFF_BH = TILE;
static constexpr int OFF_BL = 2 * TILE;
static constexpr int OFF_AL = 3 * TILE;  // only when NPASS==3

// NPASS: 2 = Ahi*Bhi + Ahi*Blo ; 3 = + Alo*Bhi
// BMODE: 0 none, 1 col-bias (bias n<256 / bias2 n>=256), 2 row-bias (bias[m])
template <int NPASS, int BMODE, bool SPLIT>
__global__ void __launch_bounds__(256) gemm_hmma(
    const __half* __restrict__ Ah, const __half* __restrict__ Al,
    const __half* __restrict__ Bh, const __half* __restrict__ Bl,
    const float* __restrict__ bias, const float* __restrict__ bias2,
    __half* __restrict__ Ch, __half* __restrict__ Cl, float* __restrict__ Cf,
    int N, int K, int lda, int ldb, int ldc, float scale,
    long sA, long sB, long sC)
{
    constexpr int STAGE = (NPASS == 3 ? 4 : 3) * TILE;
    extern __shared__ __align__(1024) char smem[];
    const uint32_t sbase = smem_u32(smem);
    const int tid = threadIdx.x;
    const int wid = tid >> 5, lane = tid & 31;
    const long z = blockIdx.z;
    const int block_row = blockIdx.y * 128;
    const int block_col = blockIdx.x * 128;

    const __half* Az_h = Ah + z * sA + (long)block_row * lda;
    const __half* Az_l = (NPASS == 3) ? Al + z * sA + (long)block_row * lda : nullptr;
    const __half* Bz_h = Bh + z * sB + (long)block_col * ldb;
    const __half* Bz_l = Bl + z * sB + (long)block_col * ldb;

    // per-thread cp.async chunk mapping (128 rows x 8 16B-chunks per tile)
    int c_row[4]; int c_co[4]; uint32_t c_so[4];
#pragma unroll
    for (int i = 0; i < 4; i++) {
        int q = tid + i * 256;
        int r = q >> 3, u = q & 7;
        c_row[i] = r;
        c_co[i] = u * 8;
        c_so[i] = (uint32_t)(r * 128 + ((u ^ (r & 7)) << 4));
    }

    auto load_stage = [&](int buf, int k0) {
        uint32_t sb = sbase + buf * STAGE;
#pragma unroll
        for (int i = 0; i < 4; i++) {
            long ga = (long)c_row[i] * lda + k0 + c_co[i];
            long gb = (long)c_row[i] * ldb + k0 + c_co[i];
            cpasync16(sb + OFF_AH + c_so[i], Az_h + ga);
            if (NPASS == 3) cpasync16(sb + OFF_AL + c_so[i], Az_l + ga);
            cpasync16(sb + OFF_BH + c_so[i], Bz_h + gb);
            cpasync16(sb + OFF_BL + c_so[i], Bz_l + gb);
        }
    };

    // warp tiling: 2(m) x 4(n), 64x32 per warp
    const int wm = wid & 1, wn = wid >> 1;
    const int arow = wm * 64 + (lane & 15);
    const uint32_t asel = ((lane >> 4) & 1) * 16;
    const uint32_t axr = (uint32_t)((arow & 7) << 4);
    const int brow = wn * 32 + (lane & 7) + ((lane & 16) ? 8 : 0);
    const uint32_t bsel = (lane & 8) ? 16u : 0u;
    const uint32_t bxr = (uint32_t)((brow & 7) << 4);

    float acc[4][4][4];
#pragma unroll
    for (int a = 0; a < 4; a++)
#pragma unroll
        for (int b = 0; b < 4; b++)
#pragma unroll
            for (int c = 0; c < 4; c++) acc[a][b][c] = 0.0f;

    const int NT = K >> 6;
    load_stage(0, 0);
    cp_commit();
    if (NT > 1) load_stage(1, 64);
    cp_commit();

    int buf = 0;
    for (int it = 0; it < NT; it++) {
        cp_wait<1>();
        __syncthreads();
        if (it + 2 < NT) load_stage((it + 2) % 3, (it + 2) << 6);
        cp_commit();

        const uint32_t sb = sbase + buf * STAGE;
#pragma unroll
        for (int kk = 0; kk < 4; kk++) {
            uint4 ah[4], al4[4], bhf[2], blf[2];
#pragma unroll
            for (int mi = 0; mi < 4; mi++) {
                uint32_t ro = (uint32_t)((arow + mi * 16) * 128) +
                              (((uint32_t)(kk * 32) + asel) ^ axr);
                ah[mi] = ldsm4(sb + OFF_AH + ro);
                if (NPASS == 3) al4[mi] = ldsm4(sb + OFF_AL + ro);
            }
#pragma unroll
            for (int pi = 0; pi < 2; pi++) {
                uint32_t ro = (uint32_t)((brow + pi * 16) * 128) +
                              (((uint32_t)(kk * 32) + bsel) ^ bxr);
                bhf[pi] = ldsm4(sb + OFF_BH + ro);
                blf[pi] = ldsm4(sb + OFF_BL + ro);
            }
#pragma unroll
            for (int mi = 0; mi < 4; mi++) {
#pragma unroll
                for (int ni = 0; ni < 4; ni++) {
                    const int pi = ni >> 1;
                    const bool up = ni & 1;
                    uint32_t bh0 = up ? bhf[pi].z : bhf[pi].x;
                    uint32_t bh1 = up ? bhf[pi].w : bhf[pi].y;
                    uint32_t bl0 = up ? blf[pi].z : blf[pi].x;
                    uint32_t bl1 = up ? blf[pi].w : blf[pi].y;
                    mma_f16(acc[mi][ni], ah[mi], bh0, bh1);     // hi*hi
                    mma_f16(acc[mi][ni], ah[mi], bl0, bl1);     // hi*lo
                    if (NPASS == 3)
                        mma_f16(acc[mi][ni], al4[mi], bh0, bh1);  // lo*hi
                }
            }
        }
        buf = (buf + 1) % 3;
    }

    // ------------------ epilogue
    const int grow0 = block_row + wm * 64 + (lane >> 2);
    const int gcol0 = block_col + wn * 32 + (lane & 3) * 2;
#pragma unroll
    for (int mi = 0; mi < 4; mi++) {
#pragma unroll
        for (int ni = 0; ni < 4; ni++) {
            float v0 = acc[mi][ni][0], v1 = acc[mi][ni][1];
            float v2 = acc[mi][ni][2], v3 = acc[mi][ni][3];
            const int r0 = grow0 + mi * 16, r1 = r0 + 8;
            const int cc = gcol0 + ni * 8;
            if (BMODE == 1) {
                float b0 = (cc < 256) ? bias[cc] : bias2[cc - 256];
                float b1 = (cc + 1 < 256) ? bias[cc + 1] : bias2[cc + 1 - 256];
                v0 += b0; v1 += b1; v2 += b0; v3 += b1;
            }
            if (BMODE == 2) {
                float ba = bias[r0], bb = bias[r1];
                v0 += ba; v1 += ba; v2 += bb; v3 += bb;
            }
            v0 *= scale; v1 *= scale; v2 *= scale; v3 *= scale;
            const long o0 = z * sC + (long)r0 * ldc + cc;
            const long o1 = z * sC + (long)r1 * ldc + cc;
            if (SPLIT) {
                uint32_t h, l;
                split2h(v0, v1, h, l);
                *(uint32_t*)(Ch + o0) = h;
                *(uint32_t*)(Cl + o0) = l;
                split2h(v2, v3, h, l);
                *(uint32_t*)(Ch + o1) = h;
                *(uint32_t*)(Cl + o1) = l;
            } else {
                *(float2*)(Cf + o0) = make_float2(v0, v1);
                *(float2*)(Cf + o1) = make_float2(v2, v3);
            }
        }
    }
}

static constexpr int SMEMB2 = 3 * 3 * TILE;  // 144 KB
static constexpr int SMEMB3 = 3 * 4 * TILE;  // 192 KB

// ------------------------------- launcher
extern "C" void kernel_launch(void* const* d_in, const int* in_sizes, int n_in,
                              void* d_out, int out_size)
{
    const float* batch = (const float*)d_in[0];
    const float* a_w   = (const float*)d_in[1];
    const float* a_b   = (const float*)d_in[2];
    const float* b_w   = (const float*)d_in[3];
    const float* b_b   = (const float*)d_in[4];
    const float* g_w   = (const float*)d_in[5];
    const float* g_b   = (const float*)d_in[6];
    float* out = (float*)d_out;

    void* p;
#define SYMH(v, s) cudaGetSymbolAddress(&p, s); __half* v = (__half*)p
    SYMH(batchH, g_batchH);   SYMH(batchL, g_batchL);
    SYMH(wTH, g_wTH);         SYMH(wTL, g_wTL);
    SYMH(gTH, g_gTH);         SYMH(gTL, g_gTL);
    SYMH(tpH, g_tpH);         SYMH(tpL, g_tpL);
    SYMH(attnH, g_attnH);     SYMH(attnL, g_attnL);
    SYMH(featsTH, g_featsTH); SYMH(featsTL, g_featsTL);
#undef SYMH

    static bool attr_done = false;
    if (!attr_done) {
        cudaFuncSetAttribute(gemm_hmma<2, 1, true>,
                             cudaFuncAttributeMaxDynamicSharedMemorySize, SMEMB2);
        cudaFuncSetAttribute(gemm_hmma<2, 2, true>,
                             cudaFuncAttributeMaxDynamicSharedMemorySize, SMEMB2);
        cudaFuncSetAttribute(gemm_hmma<3, 0, true>,
                             cudaFuncAttributeMaxDynamicSharedMemorySize, SMEMB3);
        cudaFuncSetAttribute(gemm_hmma<3, 0, false>,
                             cudaFuncAttributeMaxDynamicSharedMemorySize, SMEMB3);
        attr_done = true;
    }

    // converts
    split_kernel<<<65536, 256>>>(batch, batchH, batchL, (long)67108864);
    const dim3 tb(32, 8);
    transpose_split_kernel<<<dim3(AA / 32, FF / 32), tb>>>(a_w, wTH, wTL, FF, AA);
    transpose_split_kernel<<<dim3(AA / 32, FF / 32), tb>>>(
        b_w, wTH + 256 * 1024, wTL + 256 * 1024, FF, AA);
    transpose_split_kernel<<<dim3(FF / 32, FF / 32), tb>>>(g_w, gTH, gTL, FF, FF);

    // tp = batch @ [a_w|b_w] + bias : M=65536, N=512, K=1024 (2-pass)
    gemm_hmma<2, 1, true><<<dim3(4, 512, 1), 256, SMEMB2>>>(
        batchH, nullptr, wTH, wTL, a_b, b_b, tpH, tpL, nullptr,
        512, 1024, 1024, 1024, 512, 1.0f, 0, 0, 0);

    // featsT[t][f][s]: per t, M=1024(f), N=256(s), K=1024; A=gT (hi), bias per row f (2-pass)
    gemm_hmma<2, 2, true><<<dim3(2, 8, 256), 256, SMEMB2>>>(
        gTH, nullptr, batchH, batchL, g_b, nullptr, featsTH, featsTL, nullptr,
        256, 1024, 1024, 1024, 256, 1.0f, 0, (long)256 * 1024, (long)1024 * 256);

    // attn[t] = theta[t] @ phi[t]^T : per t M=N=256, K=256 (3-pass)
    gemm_hmma<3, 0, true><<<dim3(2, 2, 256), 256, SMEMB3>>>(
        tpH, tpL, tpH + 256, tpL + 256, nullptr, nullptr, attnH, attnL, nullptr,
        256, 256, 512, 512, 256, 1.0f, 131072, 131072, 65536);

    // out[t] = (attn[t] @ feats[t]) / 512 : per t M=256, N=1024(f), K=256 (3-pass)
    gemm_hmma<3, 0, false><<<dim3(8, 2, 256), 256, SMEMB3>>>(
        attnH, attnL, featsTH, featsTL, nullptr, nullptr, nullptr, nullptr, out,
        1024, 256, 256, 256, 1024, 1.0f / (float)(SS + TT),
        65536, (long)1024 * 256, (long)256 * 1024);
}

// round 7
// speedup vs baseline: 2.0858x; 1.6289x over previous
#include <cuda_runtime.h>
#include <cuda_fp16.h>
#include <cstdint>

// CrossInferenceBlock via fp16 split-precision mma.sync (HMMA):
//  tp    = batch @ [a_w|b_w] + bias   (65536 x 512)  2-pass (w hi+lo), out hi/lo
//  featsT[t][f][s] = (batch @ g_w + g_b)^T per t     1-pass, out hi only
//  attn[t] = theta[t] @ phi[t]^T      (256 x 256)    3-pass, out hi only
//  out[t]  = (attn[t] @ feats[t])/512                1-pass, fp32 out
// GEMM: C[m][n] = sum_k A[m,k]*B[n,k], all K-major fp16.

#define TT 256
#define SS 256
#define FF 1024
#define AA 256

// ------------------------------- static scratch
__device__ __align__(16) __half g_batchH[67108864];  // [65536][1024]
__device__ __align__(16) __half g_wTH[524288];       // [512][1024] = aT|bT
__device__ __align__(16) __half g_wTL[524288];
__device__ __align__(16) __half g_gTH[1048576];      // g_w^T
__device__ __align__(16) __half g_gTL[1048576];      // written, unused (keeps transpose simple)
__device__ __align__(16) __half g_tpH[33554432];     // [65536][512] theta|phi
__device__ __align__(16) __half g_tpL[33554432];
__device__ __align__(16) __half g_attnH[16777216];   // [65536][256]
__device__ __align__(16) __half g_featsTH[67108864]; // [256][1024][256]

// ------------------------------- helpers
__device__ __forceinline__ uint32_t smem_u32(const void* p) {
    uint32_t a;
    asm("{ .reg .u64 t; cvta.to.shared.u64 t, %1; cvt.u32.u64 %0, t; }"
        : "=r"(a) : "l"(p));
    return a;
}
__device__ __forceinline__ void cpasync16(uint32_t s, const void* g) {
    asm volatile("cp.async.cg.shared.global [%0], [%1], 16;" :: "r"(s), "l"(g));
}
__device__ __forceinline__ void cp_commit() { asm volatile("cp.async.commit_group;"); }
template <int N>
__device__ __forceinline__ void cp_wait() {
    asm volatile("cp.async.wait_group %0;" :: "n"(N));
}
__device__ __forceinline__ uint4 ldsm4(uint32_t a) {
    uint4 r;
    asm volatile("ldmatrix.sync.aligned.m8n8.x4.shared.b16 {%0,%1,%2,%3}, [%4];"
                 : "=r"(r.x), "=r"(r.y), "=r"(r.z), "=r"(r.w) : "r"(a));
    return r;
}
__device__ __forceinline__ void mma_f16(float* c, const uint4& a,
                                        uint32_t b0, uint32_t b1) {
    asm volatile(
        "mma.sync.aligned.m16n8k16.row.col.f32.f16.f16.f32 "
        "{%0,%1,%2,%3},{%4,%5,%6,%7},{%8,%9},{%0,%1,%2,%3};"
        : "+f"(c[0]), "+f"(c[1]), "+f"(c[2]), "+f"(c[3])
        : "r"(a.x), "r"(a.y), "r"(a.z), "r"(a.w), "r"(b0), "r"(b1));
}
__device__ __forceinline__ void split2h(float v0, float v1, uint32_t& h, uint32_t& l) {
    __half2 hh = __floats2half2_rn(v0, v1);
    float r0 = v0 - __low2float(hh);
    float r1 = v1 - __high2float(hh);
    __half2 ll = __floats2half2_rn(r0, r1);
    h = *(uint32_t*)&hh;
    l = *(uint32_t*)&ll;
}

// ------------------------------- converters
__global__ void cvt_kernel(const float* __restrict__ in, __half* __restrict__ oh,
                           long n) {
    long i = ((long)blockIdx.x * blockDim.x + threadIdx.x) * 8;
    if (i >= n) return;
    float4 v0 = *(const float4*)(in + i);
    float4 v1 = *(const float4*)(in + i + 4);
    __half2 a = __floats2half2_rn(v0.x, v0.y);
    __half2 b = __floats2half2_rn(v0.z, v0.w);
    __half2 c = __floats2half2_rn(v1.x, v1.y);
    __half2 d = __floats2half2_rn(v1.z, v1.w);
    *(uint4*)(oh + i) = make_uint4(*(uint32_t*)&a, *(uint32_t*)&b,
                                   *(uint32_t*)&c, *(uint32_t*)&d);
}

__global__ void transpose_split_kernel(const float* __restrict__ in,
                                       __half* __restrict__ oh,
                                       __half* __restrict__ ol, int R, int C) {
    __shared__ float t[32][33];
    int c0 = blockIdx.x * 32, r0 = blockIdx.y * 32;
    int x = threadIdx.x, y = threadIdx.y;  // 32 x 8
#pragma unroll
    for (int i = 0; i < 32; i += 8)
        t[y + i][x] = in[(long)(r0 + y + i) * C + c0 + x];
    __syncthreads();
#pragma unroll
    for (int i = 0; i < 32; i += 8) {
        float v = t[x][y + i];
        __half hb = __float2half_rn(v);
        float lo = v - __half2float(hb);
        long o = (long)(c0 + y + i) * R + r0 + x;
        oh[o] = hb;
        ol[o] = __float2half_rn(lo);
    }
}

// ------------------------------- GEMM: BM=128 BN=128 BK=64, 3-stage cp.async
static constexpr int TILE = 16384;  // 128 x 64 fp16
static constexpr int OFF_AH = 0;
static constexpr int OFF_BH = TILE;
static constexpr int OFF_BL = 2 * TILE;  // NPASS >= 2
static constexpr int OFF_AL = 3 * TILE;  // NPASS == 3

// NPASS: 1 = Ahi*Bhi ; 2 = + Ahi*Blo ; 3 = + Alo*Bhi
// BMODE: 0 none, 1 col-bias (bias n<256 / bias2 n>=256), 2 row-bias (bias[m])
// OUTM : 0 = fp16 hi only, 1 = fp16 hi+lo, 2 = fp32
template <int NPASS, int BMODE, int OUTM>
__global__ void __launch_bounds__(256, NPASS == 1 ? 2 : 1) gemm_hmma(
    const __half* __restrict__ Ah, const __half* __restrict__ Al,
    const __half* __restrict__ Bh, const __half* __restrict__ Bl,
    const float* __restrict__ bias, const float* __restrict__ bias2,
    __half* __restrict__ Ch, __half* __restrict__ Cl, float* __restrict__ Cf,
    int N, int K, int lda, int ldb, int ldc, float scale,
    long sA, long sB, long sC)
{
    constexpr int STAGE = (NPASS + 1) * TILE;
    extern __shared__ __align__(1024) char smem[];
    const uint32_t sbase = smem_u32(smem);
    const int tid = threadIdx.x;
    const int wid = tid >> 5, lane = tid & 31;
    const long z = blockIdx.z;
    const int block_row = blockIdx.y * 128;
    const int block_col = blockIdx.x * 128;

    const __half* Az_h = Ah + z * sA + (long)block_row * lda;
    const __half* Az_l = (NPASS == 3) ? Al + z * sA + (long)block_row * lda : nullptr;
    const __half* Bz_h = Bh + z * sB + (long)block_col * ldb;
    const __half* Bz_l = (NPASS >= 2) ? Bl + z * sB + (long)block_col * ldb : nullptr;

    // per-thread cp.async chunk mapping (128 rows x 8 16B-chunks per tile)
    int c_row[4]; int c_co[4]; uint32_t c_so[4];
#pragma unroll
    for (int i = 0; i < 4; i++) {
        int q = tid + i * 256;
        int r = q >> 3, u = q & 7;
        c_row[i] = r;
        c_co[i] = u * 8;
        c_so[i] = (uint32_t)(r * 128 + ((u ^ (r & 7)) << 4));
    }

    auto load_stage = [&](int buf, int k0) {
        uint32_t sb = sbase + buf * STAGE;
#pragma unroll
        for (int i = 0; i < 4; i++) {
            long ga = (long)c_row[i] * lda + k0 + c_co[i];
            long gb = (long)c_row[i] * ldb + k0 + c_co[i];
            cpasync16(sb + OFF_AH + c_so[i], Az_h + ga);
            if (NPASS == 3) cpasync16(sb + OFF_AL + c_so[i], Az_l + ga);
            cpasync16(sb + OFF_BH + c_so[i], Bz_h + gb);
            if (NPASS >= 2) cpasync16(sb + OFF_BL + c_so[i], Bz_l + gb);
        }
    };

    // warp tiling: 2(m) x 4(n), 64x32 per warp
    const int wm = wid & 1, wn = wid >> 1;
    const int arow = wm * 64 + (lane & 15);
    const uint32_t asel = ((lane >> 4) & 1) * 16;
    const uint32_t axr = (uint32_t)((arow & 7) << 4);
    const int brow = wn * 32 + (lane & 7) + ((lane & 16) ? 8 : 0);
    const uint32_t bsel = (lane & 8) ? 16u : 0u;
    const uint32_t bxr = (uint32_t)((brow & 7) << 4);

    float acc[4][4][4];
#pragma unroll
    for (int a = 0; a < 4; a++)
#pragma unroll
        for (int b = 0; b < 4; b++)
#pragma unroll
            for (int c = 0; c < 4; c++) acc[a][b][c] = 0.0f;

    const int NT = K >> 6;
    load_stage(0, 0);
    cp_commit();
    if (NT > 1) load_stage(1, 64);
    cp_commit();

    int buf = 0;
    for (int it = 0; it < NT; it++) {
        cp_wait<1>();
        __syncthreads();
        if (it + 2 < NT) load_stage((it + 2) % 3, (it + 2) << 6);
        cp_commit();

        const uint32_t sb = sbase + buf * STAGE;
#pragma unroll
        for (int kk = 0; kk < 4; kk++) {
            uint4 ah[4], al4[4], bhf[2], blf[2];
#pragma unroll
            for (int mi = 0; mi < 4; mi++) {
                uint32_t ro = (uint32_t)((arow + mi * 16) * 128) +
                              (((uint32_t)(kk * 32) + asel) ^ axr);
                ah[mi] = ldsm4(sb + OFF_AH + ro);
                if (NPASS == 3) al4[mi] = ldsm4(sb + OFF_AL + ro);
            }
#pragma unroll
            for (int pi = 0; pi < 2; pi++) {
                uint32_t ro = (uint32_t)((brow + pi * 16) * 128) +
                              (((uint32_t)(kk * 32) + bsel) ^ bxr);
                bhf[pi] = ldsm4(sb + OFF_BH + ro);
                if (NPASS >= 2) blf[pi] = ldsm4(sb + OFF_BL + ro);
            }
#pragma unroll
            for (int mi = 0; mi < 4; mi++) {
#pragma unroll
                for (int ni = 0; ni < 4; ni++) {
                    const int pi = ni >> 1;
                    const bool up = ni & 1;
                    uint32_t bh0 = up ? bhf[pi].z : bhf[pi].x;
                    uint32_t bh1 = up ? bhf[pi].w : bhf[pi].y;
                    mma_f16(acc[mi][ni], ah[mi], bh0, bh1);       // hi*hi
                    if (NPASS >= 2) {
                        uint32_t bl0 = up ? blf[pi].z : blf[pi].x;
                        uint32_t bl1 = up ? blf[pi].w : blf[pi].y;
                        mma_f16(acc[mi][ni], ah[mi], bl0, bl1);   // hi*lo
                    }
                    if (NPASS == 3)
                        mma_f16(acc[mi][ni], al4[mi], bh0, bh1);  // lo*hi
                }
            }
        }
        buf = (buf + 1) % 3;
    }

    // ------------------ epilogue
    const int grow0 = block_row + wm * 64 + (lane >> 2);
    const int gcol0 = block_col + wn * 32 + (lane & 3) * 2;
#pragma unroll
    for (int mi = 0; mi < 4; mi++) {
#pragma unroll
        for (int ni = 0; ni < 4; ni++) {
            float v0 = acc[mi][ni][0], v1 = acc[mi][ni][1];
            float v2 = acc[mi][ni][2], v3 = acc[mi][ni][3];
            const int r0 = grow0 + mi * 16, r1 = r0 + 8;
            const int cc = gcol0 + ni * 8;
            if (BMODE == 1) {
                float b0 = (cc < 256) ? bias[cc] : bias2[cc - 256];
                float b1 = (cc + 1 < 256) ? bias[cc + 1] : bias2[cc + 1 - 256];
                v0 += b0; v1 += b1; v2 += b0; v3 += b1;
            }
            if (BMODE == 2) {
                float ba = bias[r0], bb = bias[r1];
                v0 += ba; v1 += ba; v2 += bb; v3 += bb;
            }
            v0 *= scale; v1 *= scale; v2 *= scale; v3 *= scale;
            const long o0 = z * sC + (long)r0 * ldc + cc;
            const long o1 = z * sC + (long)r1 * ldc + cc;
            if (OUTM == 0) {
                __half2 p0 = __floats2half2_rn(v0, v1);
                __half2 p1 = __floats2half2_rn(v2, v3);
                *(uint32_t*)(Ch + o0) = *(uint32_t*)&p0;
                *(uint32_t*)(Ch + o1) = *(uint32_t*)&p1;
            } else if (OUTM == 1) {
                uint32_t h, l;
                split2h(v0, v1, h, l);
                *(uint32_t*)(Ch + o0) = h;
                *(uint32_t*)(Cl + o0) = l;
                split2h(v2, v3, h, l);
                *(uint32_t*)(Ch + o1) = h;
                *(uint32_t*)(Cl + o1) = l;
            } else {
                *(float2*)(Cf + o0) = make_float2(v0, v1);
                *(float2*)(Cf + o1) = make_float2(v2, v3);
            }
        }
    }
}

static constexpr int SMEMB1 = 3 * 2 * TILE;  //  96 KB
static constexpr int SMEMB2 = 3 * 3 * TILE;  // 144 KB
static constexpr int SMEMB3 = 3 * 4 * TILE;  // 192 KB

// ------------------------------- launcher
extern "C" void kernel_launch(void* const* d_in, const int* in_sizes, int n_in,
                              void* d_out, int out_size)
{
    const float* batch = (const float*)d_in[0];
    const float* a_w   = (const float*)d_in[1];
    const float* a_b   = (const float*)d_in[2];
    const float* b_w   = (const float*)d_in[3];
    const float* b_b   = (const float*)d_in[4];
    const float* g_w   = (const float*)d_in[5];
    const float* g_b   = (const float*)d_in[6];
    float* out = (float*)d_out;

    void* p;
#define SYMH(v, s) cudaGetSymbolAddress(&p, s); __half* v = (__half*)p
    SYMH(batchH, g_batchH);
    SYMH(wTH, g_wTH);         SYMH(wTL, g_wTL);
    SYMH(gTH, g_gTH);         SYMH(gTL, g_gTL);
    SYMH(tpH, g_tpH);         SYMH(tpL, g_tpL);
    SYMH(attnH, g_attnH);
    SYMH(featsTH, g_featsTH);
#undef SYMH

    static bool attr_done = false;
    if (!attr_done) {
        cudaFuncSetAttribute(gemm_hmma<2, 1, 1>,
                             cudaFuncAttributeMaxDynamicSharedMemorySize, SMEMB2);
        cudaFuncSetAttribute(gemm_hmma<1, 2, 0>,
                             cudaFuncAttributeMaxDynamicSharedMemorySize, SMEMB1);
        cudaFuncSetAttribute(gemm_hmma<3, 0, 0>,
                             cudaFuncAttributeMaxDynamicSharedMemorySize, SMEMB3);
        cudaFuncSetAttribute(gemm_hmma<1, 0, 2>,
                             cudaFuncAttributeMaxDynamicSharedMemorySize, SMEMB1);
        attr_done = true;
    }

    // converts
    cvt_kernel<<<32768, 256>>>(batch, batchH, (long)67108864);
    const dim3 tb(32, 8);
    transpose_split_kernel<<<dim3(AA / 32, FF / 32), tb>>>(a_w, wTH, wTL, FF, AA);
    transpose_split_kernel<<<dim3(AA / 32, FF / 32), tb>>>(
        b_w, wTH + 256 * 1024, wTL + 256 * 1024, FF, AA);
    transpose_split_kernel<<<dim3(FF / 32, FF / 32), tb>>>(g_w, gTH, gTL, FF, FF);

    // tp = batch @ [a_w|b_w] + bias : M=65536, N=512, K=1024 (2-pass, out hi/lo)
    gemm_hmma<2, 1, 1><<<dim3(4, 512, 1), 256, SMEMB2>>>(
        batchH, nullptr, wTH, wTL, a_b, b_b, tpH, tpL, nullptr,
        512, 1024, 1024, 1024, 512, 1.0f, 0, 0, 0);

    // featsT[t][f][s]: per t, M=1024(f), N=256(s), K=1024 (1-pass, hi only)
    gemm_hmma<1, 2, 0><<<dim3(2, 8, 256), 256, SMEMB1>>>(
        gTH, nullptr, batchH, nullptr, g_b, nullptr, featsTH, nullptr, nullptr,
        256, 1024, 1024, 1024, 256, 1.0f, 0, (long)256 * 1024, (long)1024 * 256);

    // attn[t] = theta[t] @ phi[t]^T : per t M=N=256, K=256 (3-pass, hi only)
    gemm_hmma<3, 0, 0><<<dim3(2, 2, 256), 256, SMEMB3>>>(
        tpH, tpL, tpH + 256, tpL + 256, nullptr, nullptr, attnH, nullptr, nullptr,
        256, 256, 512, 512, 256, 1.0f, 131072, 131072, 65536);

    // out[t] = (attn[t] @ feats[t]) / 512 : per t M=256, N=1024, K=256 (1-pass, fp32)
    gemm_hmma<1, 0, 2><<<dim3(8, 2, 256), 256, SMEMB1>>>(
        attnH, nullptr, featsTH, nullptr, nullptr, nullptr, nullptr, nullptr, out,
        1024, 256, 256, 256, 1024, 1.0f / (float)(SS + TT),
        65536, (long)1024 * 256, (long)256 * 1024);
}

// round 8
// speedup vs baseline: 2.5272x; 1.2116x over previous
#include <cuda_runtime.h>
#include <cuda_fp16.h>
#include <cstdint>

// CrossInferenceBlock via fp16 split-precision mma.sync (HMMA):
//  tp    = batch @ [a_w|b_w] + bias   (65536 x 512)  1-pass (w hi), out hi/lo
//  featsT[t][f][s] = (batch @ g_w + g_b)^T per t     1-pass, out hi only
//  attn[t] = theta[t] @ phi[t]^T      (256 x 256)    3-pass, out hi only
//  out[t]  = (attn[t] @ feats[t])/512                1-pass, fp32 out
// GEMM: C[m][n] = sum_k A[m,k]*B[n,k], all K-major fp16.

#define TT 256
#define SS 256
#define FF 1024
#define AA 256

// ------------------------------- static scratch
__device__ __align__(16) __half g_batchH[67108864];  // [65536][1024]
__device__ __align__(16) __half g_wTH[524288];       // [512][1024] = aT|bT (hi)
__device__ __align__(16) __half g_gTH[1048576];      // g_w^T (hi)
__device__ __align__(16) __half g_tpH[33554432];     // [65536][512] theta|phi
__device__ __align__(16) __half g_tpL[33554432];
__device__ __align__(16) __half g_attnH[16777216];   // [65536][256]
__device__ __align__(16) __half g_featsTH[67108864]; // [256][1024][256]

// ------------------------------- helpers
__device__ __forceinline__ uint32_t smem_u32(const void* p) {
    uint32_t a;
    asm("{ .reg .u64 t; cvta.to.shared.u64 t, %1; cvt.u32.u64 %0, t; }"
        : "=r"(a) : "l"(p));
    return a;
}
__device__ __forceinline__ void cpasync16(uint32_t s, const void* g) {
    asm volatile("cp.async.cg.shared.global [%0], [%1], 16;" :: "r"(s), "l"(g));
}
__device__ __forceinline__ void cp_commit() { asm volatile("cp.async.commit_group;"); }
template <int N>
__device__ __forceinline__ void cp_wait() {
    asm volatile("cp.async.wait_group %0;" :: "n"(N));
}
__device__ __forceinline__ uint4 ldsm4(uint32_t a) {
    uint4 r;
    asm volatile("ldmatrix.sync.aligned.m8n8.x4.shared.b16 {%0,%1,%2,%3}, [%4];"
                 : "=r"(r.x), "=r"(r.y), "=r"(r.z), "=r"(r.w) : "r"(a));
    return r;
}
__device__ __forceinline__ void mma_f16(float* c, const uint4& a,
                                        uint32_t b0, uint32_t b1) {
    asm volatile(
        "mma.sync.aligned.m16n8k16.row.col.f32.f16.f16.f32 "
        "{%0,%1,%2,%3},{%4,%5,%6,%7},{%8,%9},{%0,%1,%2,%3};"
        : "+f"(c[0]), "+f"(c[1]), "+f"(c[2]), "+f"(c[3])
        : "r"(a.x), "r"(a.y), "r"(a.z), "r"(a.w), "r"(b0), "r"(b1));
}
__device__ __forceinline__ void split2h(float v0, float v1, uint32_t& h, uint32_t& l) {
    __half2 hh = __floats2half2_rn(v0, v1);
    float r0 = v0 - __low2float(hh);
    float r1 = v1 - __high2float(hh);
    __half2 ll = __floats2half2_rn(r0, r1);
    h = *(uint32_t*)&hh;
    l = *(uint32_t*)&ll;
}

// ------------------------------- converters
__global__ void cvt_kernel(const float* __restrict__ in, __half* __restrict__ oh,
                           long n) {
    long i = ((long)blockIdx.x * blockDim.x + threadIdx.x) * 8;
    if (i >= n) return;
    float4 v0 = *(const float4*)(in + i);
    float4 v1 = *(const float4*)(in + i + 4);
    __half2 a = __floats2half2_rn(v0.x, v0.y);
    __half2 b = __floats2half2_rn(v0.z, v0.w);
    __half2 c = __floats2half2_rn(v1.x, v1.y);
    __half2 d = __floats2half2_rn(v1.z, v1.w);
    *(uint4*)(oh + i) = make_uint4(*(uint32_t*)&a, *(uint32_t*)&b,
                                   *(uint32_t*)&c, *(uint32_t*)&d);
}

__global__ void transpose_cvt_kernel(const float* __restrict__ in,
                                     __half* __restrict__ oh, int R, int C) {
    __shared__ float t[32][33];
    int c0 = blockIdx.x * 32, r0 = blockIdx.y * 32;
    int x = threadIdx.x, y = threadIdx.y;  // 32 x 8
#pragma unroll
    for (int i = 0; i < 32; i += 8)
        t[y + i][x] = in[(long)(r0 + y + i) * C + c0 + x];
    __syncthreads();
#pragma unroll
    for (int i = 0; i < 32; i += 8)
        oh[(long)(c0 + y + i) * R + r0 + x] = __float2half_rn(t[x][y + i]);
}

// ------------------------------- GEMM: BM=128 BN=128 BK=64, 3-stage cp.async
static constexpr int TILE = 16384;  // 128 x 64 fp16
static constexpr int OFF_AH = 0;
static constexpr int OFF_BH = TILE;
static constexpr int OFF_BL = 2 * TILE;  // NPASS >= 2
static constexpr int OFF_AL = 3 * TILE;  // NPASS == 3

// NPASS: 1 = Ahi*Bhi ; 2 = + Ahi*Blo ; 3 = + Alo*Bhi
// BMODE: 0 none, 1 col-bias (bias n<256 / bias2 n>=256), 2 row-bias (bias[m])
// OUTM : 0 = fp16 hi only, 1 = fp16 hi+lo, 2 = fp32
template <int NPASS, int BMODE, int OUTM>
__global__ void __launch_bounds__(256, NPASS == 1 ? 2 : 1) gemm_hmma(
    const __half* __restrict__ Ah, const __half* __restrict__ Al,
    const __half* __restrict__ Bh, const __half* __restrict__ Bl,
    const float* __restrict__ bias, const float* __restrict__ bias2,
    __half* __restrict__ Ch, __half* __restrict__ Cl, float* __restrict__ Cf,
    int N, int K, int lda, int ldb, int ldc, float scale,
    long sA, long sB, long sC)
{
    constexpr int STAGE = (NPASS + 1) * TILE;
    extern __shared__ __align__(1024) char smem[];
    const uint32_t sbase = smem_u32(smem);
    const int tid = threadIdx.x;
    const int wid = tid >> 5, lane = tid & 31;
    const long z = blockIdx.z;
    const int block_row = blockIdx.y * 128;
    const int block_col = blockIdx.x * 128;

    const __half* Az_h = Ah + z * sA + (long)block_row * lda;
    const __half* Az_l = (NPASS == 3) ? Al + z * sA + (long)block_row * lda : nullptr;
    const __half* Bz_h = Bh + z * sB + (long)block_col * ldb;
    const __half* Bz_l = (NPASS >= 2) ? Bl + z * sB + (long)block_col * ldb : nullptr;

    // per-thread cp.async chunk mapping (128 rows x 8 16B-chunks per tile)
    int c_row[4]; int c_co[4]; uint32_t c_so[4];
#pragma unroll
    for (int i = 0; i < 4; i++) {
        int q = tid + i * 256;
        int r = q >> 3, u = q & 7;
        c_row[i] = r;
        c_co[i] = u * 8;
        c_so[i] = (uint32_t)(r * 128 + ((u ^ (r & 7)) << 4));
    }

    auto load_stage = [&](int buf, int k0) {
        uint32_t sb = sbase + buf * STAGE;
#pragma unroll
        for (int i = 0; i < 4; i++) {
            long ga = (long)c_row[i] * lda + k0 + c_co[i];
            long gb = (long)c_row[i] * ldb + k0 + c_co[i];
            cpasync16(sb + OFF_AH + c_so[i], Az_h + ga);
            if (NPASS == 3) cpasync16(sb + OFF_AL + c_so[i], Az_l + ga);
            cpasync16(sb + OFF_BH + c_so[i], Bz_h + gb);
            if (NPASS >= 2) cpasync16(sb + OFF_BL + c_so[i], Bz_l + gb);
        }
    };

    // warp tiling: 2(m) x 4(n), 64x32 per warp
    const int wm = wid & 1, wn = wid >> 1;
    const int arow = wm * 64 + (lane & 15);
    const uint32_t asel = ((lane >> 4) & 1) * 16;
    const uint32_t axr = (uint32_t)((arow & 7) << 4);
    const int brow = wn * 32 + (lane & 7) + ((lane & 16) ? 8 : 0);
    const uint32_t bsel = (lane & 8) ? 16u : 0u;
    const uint32_t bxr = (uint32_t)((brow & 7) << 4);

    float acc[4][4][4];
#pragma unroll
    for (int a = 0; a < 4; a++)
#pragma unroll
        for (int b = 0; b < 4; b++)
#pragma unroll
            for (int c = 0; c < 4; c++) acc[a][b][c] = 0.0f;

    const int NT = K >> 6;
    load_stage(0, 0);
    cp_commit();
    if (NT > 1) load_stage(1, 64);
    cp_commit();

    int buf = 0;
    for (int it = 0; it < NT; it++) {
        cp_wait<1>();
        __syncthreads();
        if (it + 2 < NT) load_stage((it + 2) % 3, (it + 2) << 6);
        cp_commit();

        const uint32_t sb = sbase + buf * STAGE;
#pragma unroll
        for (int kk = 0; kk < 4; kk++) {
            uint4 ah[4], al4[4], bhf[2], blf[2];
#pragma unroll
            for (int mi = 0; mi < 4; mi++) {
                uint32_t ro = (uint32_t)((arow + mi * 16) * 128) +
                              (((uint32_t)(kk * 32) + asel) ^ axr);
                ah[mi] = ldsm4(sb + OFF_AH + ro);
                if (NPASS == 3) al4[mi] = ldsm4(sb + OFF_AL + ro);
            }
#pragma unroll
            for (int pi = 0; pi < 2; pi++) {
                uint32_t ro = (uint32_t)((brow + pi * 16) * 128) +
                              (((uint32_t)(kk * 32) + bsel) ^ bxr);
                bhf[pi] = ldsm4(sb + OFF_BH + ro);
                if (NPASS >= 2) blf[pi] = ldsm4(sb + OFF_BL + ro);
            }
#pragma unroll
            for (int mi = 0; mi < 4; mi++) {
#pragma unroll
                for (int ni = 0; ni < 4; ni++) {
                    const int pi = ni >> 1;
                    const bool up = ni & 1;
                    uint32_t bh0 = up ? bhf[pi].z : bhf[pi].x;
                    uint32_t bh1 = up ? bhf[pi].w : bhf[pi].y;
                    mma_f16(acc[mi][ni], ah[mi], bh0, bh1);       // hi*hi
                    if (NPASS >= 2) {
                        uint32_t bl0 = up ? blf[pi].z : blf[pi].x;
                        uint32_t bl1 = up ? blf[pi].w : blf[pi].y;
                        mma_f16(acc[mi][ni], ah[mi], bl0, bl1);   // hi*lo
                    }
                    if (NPASS == 3)
                        mma_f16(acc[mi][ni], al4[mi], bh0, bh1);  // lo*hi
                }
            }
        }
        buf = (buf + 1) % 3;
    }

    // ------------------ epilogue
    const int grow0 = block_row + wm * 64 + (lane >> 2);
    const int gcol0 = block_col + wn * 32 + (lane & 3) * 2;
#pragma unroll
    for (int mi = 0; mi < 4; mi++) {
#pragma unroll
        for (int ni = 0; ni < 4; ni++) {
            float v0 = acc[mi][ni][0], v1 = acc[mi][ni][1];
            float v2 = acc[mi][ni][2], v3 = acc[mi][ni][3];
            const int r0 = grow0 + mi * 16, r1 = r0 + 8;
            const int cc = gcol0 + ni * 8;
            if (BMODE == 1) {
                float b0 = (cc < 256) ? bias[cc] : bias2[cc - 256];
                float b1 = (cc + 1 < 256) ? bias[cc + 1] : bias2[cc + 1 - 256];
                v0 += b0; v1 += b1; v2 += b0; v3 += b1;
            }
            if (BMODE == 2) {
                float ba = bias[r0], bb = bias[r1];
                v0 += ba; v1 += ba; v2 += bb; v3 += bb;
            }
            v0 *= scale; v1 *= scale; v2 *= scale; v3 *= scale;
            const long o0 = z * sC + (long)r0 * ldc + cc;
            const long o1 = z * sC + (long)r1 * ldc + cc;
            if (OUTM == 0) {
                __half2 p0 = __floats2half2_rn(v0, v1);
                __half2 p1 = __floats2half2_rn(v2, v3);
                *(uint32_t*)(Ch + o0) = *(uint32_t*)&p0;
                *(uint32_t*)(Ch + o1) = *(uint32_t*)&p1;
            } else if (OUTM == 1) {
                uint32_t h, l;
                split2h(v0, v1, h, l);
                *(uint32_t*)(Ch + o0) = h;
                *(uint32_t*)(Cl + o0) = l;
                split2h(v2, v3, h, l);
                *(uint32_t*)(Ch + o1) = h;
                *(uint32_t*)(Cl + o1) = l;
            } else {
                *(float2*)(Cf + o0) = make_float2(v0, v1);
                *(float2*)(Cf + o1) = make_float2(v2, v3);
            }
        }
    }
}

static constexpr int SMEMB1 = 3 * 2 * TILE;  //  96 KB
static constexpr int SMEMB3 = 3 * 4 * TILE;  // 192 KB

// ------------------------------- launcher
extern "C" void kernel_launch(void* const* d_in, const int* in_sizes, int n_in,
                              void* d_out, int out_size)
{
    const float* batch = (const float*)d_in[0];
    const float* a_w   = (const float*)d_in[1];
    const float* a_b   = (const float*)d_in[2];
    const float* b_w   = (const float*)d_in[3];
    const float* b_b   = (const float*)d_in[4];
    const float* g_w   = (const float*)d_in[5];
    const float* g_b   = (const float*)d_in[6];
    float* out = (float*)d_out;

    void* p;
#define SYMH(v, s) cudaGetSymbolAddress(&p, s); __half* v = (__half*)p
    SYMH(batchH, g_batchH);
    SYMH(wTH, g_wTH);
    SYMH(gTH, g_gTH);
    SYMH(tpH, g_tpH);         SYMH(tpL, g_tpL);
    SYMH(attnH, g_attnH);
    SYMH(featsTH, g_featsTH);
#undef SYMH

    static bool attr_done = false;
    if (!attr_done) {
        cudaFuncSetAttribute(gemm_hmma<1, 1, 1>,
                             cudaFuncAttributeMaxDynamicSharedMemorySize, SMEMB1);
        cudaFuncSetAttribute(gemm_hmma<1, 2, 0>,
                             cudaFuncAttributeMaxDynamicSharedMemorySize, SMEMB1);
        cudaFuncSetAttribute(gemm_hmma<3, 0, 0>,
                             cudaFuncAttributeMaxDynamicSharedMemorySize, SMEMB3);
        cudaFuncSetAttribute(gemm_hmma<1, 0, 2>,
                             cudaFuncAttributeMaxDynamicSharedMemorySize, SMEMB1);
        attr_done = true;
    }

    // converts
    cvt_kernel<<<32768, 256>>>(batch, batchH, (long)67108864);
    const dim3 tb(32, 8);
    transpose_cvt_kernel<<<dim3(AA / 32, FF / 32), tb>>>(a_w, wTH, FF, AA);
    transpose_cvt_kernel<<<dim3(AA / 32, FF / 32), tb>>>(
        b_w, wTH + 256 * 1024, FF, AA);
    transpose_cvt_kernel<<<dim3(FF / 32, FF / 32), tb>>>(g_w, gTH, FF, FF);

    // tp = batch @ [a_w|b_w] + bias : M=65536, N=512, K=1024 (1-pass, out hi/lo)
    gemm_hmma<1, 1, 1><<<dim3(4, 512, 1), 256, SMEMB1>>>(
        batchH, nullptr, wTH, nullptr, a_b, b_b, tpH, tpL, nullptr,
        512, 1024, 1024, 1024, 512, 1.0f, 0, 0, 0);

    // featsT[t][f][s]: per t, M=1024(f), N=256(s), K=1024 (1-pass, hi only)
    gemm_hmma<1, 2, 0><<<dim3(2, 8, 256), 256, SMEMB1>>>(
        gTH, nullptr, batchH, nullptr, g_b, nullptr, featsTH, nullptr, nullptr,
        256, 1024, 1024, 1024, 256, 1.0f, 0, (long)256 * 1024, (long)1024 * 256);

    // attn[t] = theta[t] @ phi[t]^T : per t M=N=256, K=256 (3-pass, hi only)
    gemm_hmma<3, 0, 0><<<dim3(2, 2, 256), 256, SMEMB3>>>(
        tpH, tpL, tpH + 256, tpL + 256, nullptr, nullptr, attnH, nullptr, nullptr,
        256, 256, 512, 512, 256, 1.0f, 131072, 131072, 65536);

    // out[t] = (attn[t] @ feats[t]) / 512 : per t M=256, N=1024, K=256 (1-pass, fp32)
    gemm_hmma<1, 0, 2><<<dim3(8, 2, 256), 256, SMEMB1>>>(
        attnH, nullptr, featsTH, nullptr, nullptr, nullptr, nullptr, nullptr, out,
        1024, 256, 256, 256, 1024, 1.0f / (float)(SS + TT),
        65536, (long)1024 * 256, (long)256 * 1024);
}